// round 5
// baseline (speedup 1.0000x reference)
#include <cuda_runtime.h>
#include <cuda_bf16.h>

#define NN 50000
#define EE 800000
#define NEG_SLOPE 0.2f

// ---------------------------------------------------------------------------
// Scratch (device globals; referenced ONLY from device code — passing a
// __device__ symbol as a kernel argument from host gives a garbage pointer)
// ---------------------------------------------------------------------------
__device__ __align__(16) float    g_feat[NN * 128];
__device__ __align__(16) float    g_rst [NN * 128];
__device__ __align__(16) float    g_h   [NN * 64];
__device__ __align__(16) float    g_el  [NN * 2];
__device__ __align__(16) float    g_er  [NN * 2];
__device__ __align__(16) unsigned g_m   [NN * 2];
__device__ __align__(16) float    g_s   [NN * 2];
__device__ __align__(16) float    g_e   [EE * 2];

__device__ const float* r_x;
__device__ const int*   r_src;
__device__ const int*   r_dst;
__device__ const float* r_W[3];
__device__ const float* r_al[3];
__device__ const float* r_ar[3];
__device__ const float* r_b[3];

struct InPtrs {
    const void* p[16];
    int sz[16];
    int n;
};

__device__ __forceinline__ int norm_size(int sz) {
    switch (sz) {
        case 6400000: case 800000: case 8192: case 4096: case 128: case 64:
            return sz;
        case 25600000: return 6400000;
        case 3200000:  return 800000;
        case 32768:    return 8192;
        case 16384:    return 4096;
        case 512:      return 128;
        case 256:      return 64;
        default:       return -1;
    }
}

// ---------------------------------------------------------------------------
// Content/shape-based input classification with positional fallback.
// ---------------------------------------------------------------------------
__global__ __launch_bounds__(256) void classify_kernel(InPtrs in) {
    __shared__ float sred[256];
    __shared__ int sh8192[2];
    __shared__ int s_ok;

    if (threadIdx.x == 0) {
        int c = 0;
        sh8192[0] = sh8192[1] = 0;
        for (int i = 0; i < in.n && i < 16; i++)
            if (norm_size(in.sz[i]) == 8192 && c < 2) sh8192[c++] = i;
        s_ok = (c == 2);
    }
    __syncthreads();

    float q[2];
    for (int t = 0; t < 2; t++) {
        const float* p = (const float*)in.p[sh8192[t]];
        float s = 0.f;
        if (s_ok)
            for (int i = threadIdx.x; i < 8192; i += 256) { float v = p[i]; s += v * v; }
        sred[threadIdx.x] = s;
        __syncthreads();
        for (int st = 128; st > 0; st >>= 1) {
            if (threadIdx.x < st) sred[threadIdx.x] += sred[threadIdx.x + st];
            __syncthreads();
        }
        q[t] = sred[0];
        __syncthreads();
    }

    if (threadIdx.x != 0) return;

    int iX = -1, iW1 = -1, i800k[2] = {-1, -1}, i128[3] = {-1, -1, -1}, i64[6];
    int c800k = 0, c128 = 0, c64 = 0;
    for (int i = 0; i < 6; i++) i64[i] = -1;
    for (int i = 0; i < in.n && i < 16; i++) {
        int n = norm_size(in.sz[i]);
        if      (n == 6400000) iX = i;
        else if (n == 4096)    iW1 = i;
        else if (n == 800000)  { if (c800k < 2) i800k[c800k++] = i; }
        else if (n == 128)     { if (c128 < 3)  i128[c128++]  = i; }
        else if (n == 64)      { if (c64 < 6)   i64[c64++]    = i; }
    }

    bool ok = s_ok && iX >= 0 && iW1 >= 0 && c800k == 2 && c128 == 3 && c64 == 6;

    int ix, isrc, idst, iW0, iW2, ial[3], iar[3], ib[3];
    if (!ok) {
        ix = 0; isrc = 1; idst = 2;
        iW0 = 3;  ial[0] = 4;  iar[0] = 5;  ib[0] = 6;
        iW1 = 7;  ial[1] = 8;  iar[1] = 9;  ib[1] = 10;
        iW2 = 11; ial[2] = 12; iar[2] = 13; ib[2] = 14;
    } else {
        ix  = iX;
        iW0 = (q[0] < q[1]) ? sh8192[0] : sh8192[1];   // ssq ~64 vs ~128
        iW2 = (q[0] < q[1]) ? sh8192[1] : sh8192[0];

        int zs[6], zn = 0, ns[6], nn = 0;
        for (int g = 0; g < 6; g++) {
            const float* p = (const float*)in.p[i64[g]];
            float s = 0.f;
            for (int k = 0; k < 64; k++) s += fabsf(p[k]);
            if (s == 0.0f) { if (zn < 6) zs[zn++] = g; }
            else           { if (nn < 6) ns[nn++] = g; }
        }
        bool interleaved = (zn < 1) || (zs[0] == 2);
        if (zn >= 2 && nn >= 4) {
            ib[0] = i64[zs[0]]; ib[1] = i64[zs[1]];
            if (interleaved) { ial[0]=i64[ns[0]]; iar[0]=i64[ns[1]]; ial[1]=i64[ns[2]]; iar[1]=i64[ns[3]]; }
            else             { ial[0]=i64[ns[0]]; ial[1]=i64[ns[1]]; iar[0]=i64[ns[2]]; iar[1]=i64[ns[3]]; }
        } else {
            ib[0]=i64[2]; ib[1]=i64[5]; ial[0]=i64[0]; iar[0]=i64[1]; ial[1]=i64[3]; iar[1]=i64[4];
        }

        int a2 = -1, r2 = -1, bz = -1;
        for (int g = 0; g < 3; g++) {
            const float* p = (const float*)in.p[i128[g]];
            float s = 0.f;
            for (int k = 0; k < 128; k++) s += fabsf(p[k]);
            if (s == 0.0f)   bz = i128[g];
            else if (a2 < 0) a2 = i128[g];
            else             r2 = i128[g];
        }
        ial[2] = a2; iar[2] = r2; ib[2] = (bz >= 0) ? bz : i128[2];

        isrc = interleaved ? i800k[0] : i800k[1];
        idst = interleaved ? i800k[1] : i800k[0];
    }

    r_x    = (const float*)in.p[ix];
    r_src  = (const int*)  in.p[isrc];
    r_dst  = (const int*)  in.p[idst];
    r_W[0] = (const float*)in.p[iW0];
    r_W[1] = (const float*)in.p[iW1];
    r_W[2] = (const float*)in.p[iW2];
    for (int l = 0; l < 3; l++) {
        r_al[l] = (const float*)in.p[ial[l]];
        r_ar[l] = (const float*)in.p[iar[l]];
        r_b [l] = (const float*)in.p[ib[l]];
    }
}

// ---------------------------------------------------------------------------
__device__ __forceinline__ unsigned encf(float f) {
    unsigned u = __float_as_uint(f);
    return (u & 0x80000000u) ? ~u : (u | 0x80000000u);
}
__device__ __forceinline__ float decf(unsigned u) {
    return __uint_as_float((u & 0x80000000u) ? (u & 0x7FFFFFFFu) : ~u);
}

__global__ void zero_scratch(int rst_elems) {
    int i = blockIdx.x * blockDim.x + threadIdx.x;
    if (i < NN * 2) { g_m[i] = 0u; g_s[i] = 0.0f; }
    if (i < rst_elems) g_rst[i] = 0.0f;
}

// ---------------------------------------------------------------------------
// GEMM: g_feat[N, C] = X[N, K] @ W[K, C]  (writes g_feat directly)
// ---------------------------------------------------------------------------
template <int K, int C, int LAYER>
__global__ __launch_bounds__(256) void gemm_kernel() {
    constexpr int BM  = 64;
    constexpr int BK  = 32;
    constexpr int TCG = C / 4;
    constexpr int TM  = (BM * C) / 1024;
    constexpr int NVW = C / 32;

    const float* __restrict__ X = (LAYER == 0) ? r_x : g_h;
    const float* __restrict__ W = r_W[LAYER];

    __shared__ float xs[BM][BK];
    __shared__ float ws[BK][C];

    int tid  = threadIdx.x;
    int tc   = tid % TCG;
    int tr   = tid / TCG;
    int row0 = blockIdx.x * BM;

    float acc[TM][4];
#pragma unroll
    for (int i = 0; i < TM; i++)
#pragma unroll
        for (int j = 0; j < 4; j++) acc[i][j] = 0.0f;

    for (int k0 = 0; k0 < K; k0 += BK) {
#pragma unroll
        for (int v = 0; v < 2; v++) {
            int i4 = v * 256 + tid;
            int r  = i4 >> 3;
            int c4 = i4 & 7;
            float4 val = make_float4(0.f, 0.f, 0.f, 0.f);
            if (row0 + r < NN)
                val = *(const float4*)&X[(size_t)(row0 + r) * K + k0 + c4 * 4];
            *(float4*)&xs[r][c4 * 4] = val;
        }
#pragma unroll
        for (int v = 0; v < NVW; v++) {
            int i4 = v * 256 + tid;
            int k  = i4 / (C / 4);
            int c4 = i4 % (C / 4);
            *(float4*)&ws[k][c4 * 4] = *(const float4*)&W[(size_t)(k0 + k) * C + c4 * 4];
        }
        __syncthreads();

#pragma unroll
        for (int kk = 0; kk < BK; kk++) {
            float4 w4 = *(float4*)&ws[kk][tc * 4];
#pragma unroll
            for (int i = 0; i < TM; i++) {
                float xv = xs[tr * TM + i][kk];
                acc[i][0] += xv * w4.x;
                acc[i][1] += xv * w4.y;
                acc[i][2] += xv * w4.z;
                acc[i][3] += xv * w4.w;
            }
        }
        __syncthreads();
    }

#pragma unroll
    for (int i = 0; i < TM; i++) {
        int r = row0 + tr * TM + i;
        if (r < NN) {
            float4 o = make_float4(acc[i][0], acc[i][1], acc[i][2], acc[i][3]);
            *(float4*)&g_feat[(size_t)r * C + tc * 4] = o;
        }
    }
}

// ---------------------------------------------------------------------------
template <int D, int LAYER>
__global__ void attn_kernel() {
    int i = blockIdx.x * blockDim.x + threadIdx.x;
    if (i >= NN * 2) return;
    int h = i & 1;
    const float* f = g_feat + (size_t)(i >> 1) * (2 * D) + h * D;
    const float* a = r_al[LAYER] + h * D;
    const float* b = r_ar[LAYER] + h * D;
    float sa = 0.f, sb = 0.f;
#pragma unroll
    for (int d = 0; d < D; d++) {
        float fv = f[d];
        sa += fv * a[d];
        sb += fv * b[d];
    }
    g_el[i] = sa;
    g_er[i] = sb;
}

// ---------------------------------------------------------------------------
__global__ void edge_pass1() {
    int t = blockIdx.x * blockDim.x + threadIdx.x;
    if (t >= EE * 2) return;
    int eid = t >> 1, h = t & 1;
    int s = r_src[eid], d = r_dst[eid];
    if ((unsigned)s >= NN || (unsigned)d >= NN) return;
    float v = g_el[s * 2 + h] + g_er[d * 2 + h];
    v = v > 0.f ? v : NEG_SLOPE * v;
    g_e[t] = v;
    atomicMax(&g_m[d * 2 + h], encf(v));
}

__global__ void edge_pass2() {
    int t = blockIdx.x * blockDim.x + threadIdx.x;
    if (t >= EE * 2) return;
    int eid = t >> 1, h = t & 1;
    int d = r_dst[eid];
    if ((unsigned)d >= NN) return;
    float m  = decf(g_m[d * 2 + h]);
    float ex = __expf(g_e[t] - m);
    g_e[t] = ex;
    atomicAdd(&g_s[d * 2 + h], ex);
}

// 8 lanes per (edge, head): coalesced gather + scatter
template <int D>
__global__ void edge_pass3() {
    int t = blockIdx.x * blockDim.x + threadIdx.x;
    if (t >= EE * 2 * 8) return;
    int lane = t & 7, eh = t >> 3;
    int eid = eh >> 1, h = eh & 1;
    int s = r_src[eid], d = r_dst[eid];
    if ((unsigned)s >= NN || (unsigned)d >= NN) return;
    float alpha = g_e[eh] / g_s[d * 2 + h];
    const float* f = g_feat + (size_t)s * (2 * D) + h * D;
    float*       r = g_rst  + (size_t)d * (2 * D) + h * D;
#pragma unroll
    for (int k = 0; k < D / 8; k++)
        atomicAdd(&r[lane + 8 * k], f[lane + 8 * k] * alpha);
}

// ---------------------------------------------------------------------------
template <int LAYER>
__global__ void epi01() {
    int i = blockIdx.x * blockDim.x + threadIdx.x;
    if (i >= NN * 64) return;
    float v = g_rst[i] + r_b[LAYER][i & 63];
    g_h[i] = v > 0.f ? v : 0.f;
}

__global__ void epi2(float* __restrict__ out) {
    int i = blockIdx.x * blockDim.x + threadIdx.x;
    if (i >= NN * 64) return;
    int n = i >> 6, j = i & 63;
    const float* b = r_b[2];
    float v0 = g_rst[(size_t)n * 128 + j]      + b[j];
    float v1 = g_rst[(size_t)n * 128 + 64 + j] + b[64 + j];
    out[i] = 0.5f * (v0 + v1);
}

// ---------------------------------------------------------------------------
extern "C" void kernel_launch(void* const* d_in, const int* in_sizes, int n_in,
                              void* d_out, int out_size) {
    InPtrs in;
    in.n = (n_in < 16) ? n_in : 16;
    for (int i = 0; i < 16; i++) {
        in.p[i]  = (i < n_in) ? d_in[i] : nullptr;
        in.sz[i] = (i < n_in) ? in_sizes[i] : 0;
    }
    float* out = (float*)d_out;

    const int BS = 256;
    const int gN2   = (NN * 2  + BS - 1) / BS;
    const int gE2   = (EE * 2  + BS - 1) / BS;
    const int gE16  = (EE * 16 + BS - 1) / BS;
    const int gN64  = (NN * 64 + BS - 1) / BS;
    const int gN128 = (NN * 128 + BS - 1) / BS;
    const int gGemm = (NN + 63) / 64;

    classify_kernel<<<1, 256>>>(in);

    // ---- Layer 0: 128 -> 64 ----
    zero_scratch<<<gN64, BS>>>(NN * 64);
    gemm_kernel<128, 64, 0><<<gGemm, BS>>>();
    attn_kernel<32, 0><<<gN2, BS>>>();
    edge_pass1<<<gE2, BS>>>();
    edge_pass2<<<gE2, BS>>>();
    edge_pass3<32><<<gE16, BS>>>();
    epi01<0><<<gN64, BS>>>();

    // ---- Layer 1: 64 -> 64 ----
    zero_scratch<<<gN64, BS>>>(NN * 64);
    gemm_kernel<64, 64, 1><<<gGemm, BS>>>();
    attn_kernel<32, 1><<<gN2, BS>>>();
    edge_pass1<<<gE2, BS>>>();
    edge_pass2<<<gE2, BS>>>();
    edge_pass3<32><<<gE16, BS>>>();
    epi01<1><<<gN64, BS>>>();

    // ---- Layer 2: 64 -> 128 (2 heads x 64), mean over heads ----
    zero_scratch<<<gN128, BS>>>(NN * 128);
    gemm_kernel<64, 128, 2><<<gGemm, BS>>>();
    attn_kernel<64, 2><<<gN2, BS>>>();
    edge_pass1<<<gE2, BS>>>();
    edge_pass2<<<gE2, BS>>>();
    edge_pass3<64><<<gE16, BS>>>();
    epi2<<<gN64, BS>>>(out);
}

// round 6
// speedup vs baseline: 1.2170x; 1.2170x over previous
#include <cuda_runtime.h>
#include <cuda_bf16.h>

#define NN 50000
#define EE 800000
#define NEG_SLOPE 0.2f

// ---------------------------------------------------------------------------
// Scratch (device globals; referenced ONLY from device code)
// ---------------------------------------------------------------------------
__device__ __align__(16) float    g_feat[NN * 128];
__device__ __align__(16) float    g_rst [NN * 128];
__device__ __align__(16) float    g_h   [NN * 64];
__device__ __align__(16) float    g_el  [NN * 2];
__device__ __align__(16) float    g_er  [NN * 2];
__device__ __align__(16) unsigned g_m   [NN * 2];
__device__ __align__(16) float    g_s   [NN * 2];
__device__ __align__(16) float    g_e   [EE * 2];

__device__ const float* r_x;
__device__ const int*   r_src;
__device__ const int*   r_dst;
__device__ const float* r_W[3];
__device__ const float* r_al[3];
__device__ const float* r_ar[3];
__device__ const float* r_b[3];

struct InPtrs {
    const void* p[16];
    int sz[16];
    int n;
};

__device__ __forceinline__ int norm_size(int sz) {
    switch (sz) {
        case 6400000: case 800000: case 8192: case 4096: case 128: case 64:
            return sz;
        case 25600000: return 6400000;
        case 3200000:  return 800000;
        case 32768:    return 8192;
        case 16384:    return 4096;
        case 512:      return 128;
        case 256:      return 64;
        default:       return -1;
    }
}

// ---------------------------------------------------------------------------
// Content/shape-based input classification with positional fallback.
// ---------------------------------------------------------------------------
__global__ __launch_bounds__(256) void classify_kernel(InPtrs in) {
    __shared__ float sred[256];
    __shared__ int sh8192[2];
    __shared__ int s_ok;

    if (threadIdx.x == 0) {
        int c = 0;
        sh8192[0] = sh8192[1] = 0;
        for (int i = 0; i < in.n && i < 16; i++)
            if (norm_size(in.sz[i]) == 8192 && c < 2) sh8192[c++] = i;
        s_ok = (c == 2);
    }
    __syncthreads();

    float q[2];
    for (int t = 0; t < 2; t++) {
        const float* p = (const float*)in.p[sh8192[t]];
        float s = 0.f;
        if (s_ok)
            for (int i = threadIdx.x; i < 8192; i += 256) { float v = p[i]; s += v * v; }
        sred[threadIdx.x] = s;
        __syncthreads();
        for (int st = 128; st > 0; st >>= 1) {
            if (threadIdx.x < st) sred[threadIdx.x] += sred[threadIdx.x + st];
            __syncthreads();
        }
        q[t] = sred[0];
        __syncthreads();
    }

    if (threadIdx.x != 0) return;

    int iX = -1, iW1 = -1, i800k[2] = {-1, -1}, i128[3] = {-1, -1, -1}, i64[6];
    int c800k = 0, c128 = 0, c64 = 0;
    for (int i = 0; i < 6; i++) i64[i] = -1;
    for (int i = 0; i < in.n && i < 16; i++) {
        int n = norm_size(in.sz[i]);
        if      (n == 6400000) iX = i;
        else if (n == 4096)    iW1 = i;
        else if (n == 800000)  { if (c800k < 2) i800k[c800k++] = i; }
        else if (n == 128)     { if (c128 < 3)  i128[c128++]  = i; }
        else if (n == 64)      { if (c64 < 6)   i64[c64++]    = i; }
    }

    bool ok = s_ok && iX >= 0 && iW1 >= 0 && c800k == 2 && c128 == 3 && c64 == 6;

    int ix, isrc, idst, iW0, iW2, ial[3], iar[3], ib[3];
    if (!ok) {
        ix = 0; isrc = 1; idst = 2;
        iW0 = 3;  ial[0] = 4;  iar[0] = 5;  ib[0] = 6;
        iW1 = 7;  ial[1] = 8;  iar[1] = 9;  ib[1] = 10;
        iW2 = 11; ial[2] = 12; iar[2] = 13; ib[2] = 14;
    } else {
        ix  = iX;
        iW0 = (q[0] < q[1]) ? sh8192[0] : sh8192[1];
        iW2 = (q[0] < q[1]) ? sh8192[1] : sh8192[0];

        int zs[6], zn = 0, ns[6], nn = 0;
        for (int g = 0; g < 6; g++) {
            const float* p = (const float*)in.p[i64[g]];
            float s = 0.f;
            for (int k = 0; k < 64; k++) s += fabsf(p[k]);
            if (s == 0.0f) { if (zn < 6) zs[zn++] = g; }
            else           { if (nn < 6) ns[nn++] = g; }
        }
        bool interleaved = (zn < 1) || (zs[0] == 2);
        if (zn >= 2 && nn >= 4) {
            ib[0] = i64[zs[0]]; ib[1] = i64[zs[1]];
            if (interleaved) { ial[0]=i64[ns[0]]; iar[0]=i64[ns[1]]; ial[1]=i64[ns[2]]; iar[1]=i64[ns[3]]; }
            else             { ial[0]=i64[ns[0]]; ial[1]=i64[ns[1]]; iar[0]=i64[ns[2]]; iar[1]=i64[ns[3]]; }
        } else {
            ib[0]=i64[2]; ib[1]=i64[5]; ial[0]=i64[0]; iar[0]=i64[1]; ial[1]=i64[3]; iar[1]=i64[4];
        }

        int a2 = -1, r2 = -1, bz = -1;
        for (int g = 0; g < 3; g++) {
            const float* p = (const float*)in.p[i128[g]];
            float s = 0.f;
            for (int k = 0; k < 128; k++) s += fabsf(p[k]);
            if (s == 0.0f)   bz = i128[g];
            else if (a2 < 0) a2 = i128[g];
            else             r2 = i128[g];
        }
        ial[2] = a2; iar[2] = r2; ib[2] = (bz >= 0) ? bz : i128[2];

        isrc = interleaved ? i800k[0] : i800k[1];
        idst = interleaved ? i800k[1] : i800k[0];
    }

    r_x    = (const float*)in.p[ix];
    r_src  = (const int*)  in.p[isrc];
    r_dst  = (const int*)  in.p[idst];
    r_W[0] = (const float*)in.p[iW0];
    r_W[1] = (const float*)in.p[iW1];
    r_W[2] = (const float*)in.p[iW2];
    for (int l = 0; l < 3; l++) {
        r_al[l] = (const float*)in.p[ial[l]];
        r_ar[l] = (const float*)in.p[iar[l]];
        r_b [l] = (const float*)in.p[ib[l]];
    }
}

// ---------------------------------------------------------------------------
__device__ __forceinline__ unsigned encf(float f) {
    unsigned u = __float_as_uint(f);
    return (u & 0x80000000u) ? ~u : (u | 0x80000000u);
}
__device__ __forceinline__ float decf(unsigned u) {
    return __uint_as_float((u & 0x80000000u) ? (u & 0x7FFFFFFFu) : ~u);
}

__global__ void zero_scratch(int rst_vec4) {
    int i = blockIdx.x * blockDim.x + threadIdx.x;
    if (i < NN * 2) { g_m[i] = 0u; g_s[i] = 0.0f; }
    if (i < rst_vec4) ((float4*)g_rst)[i] = make_float4(0.f, 0.f, 0.f, 0.f);
}

// ---------------------------------------------------------------------------
// GEMM: g_feat[N, C] = X[N, K] @ W[K, C]
// ---------------------------------------------------------------------------
template <int K, int C, int LAYER>
__global__ __launch_bounds__(256) void gemm_kernel() {
    constexpr int BM  = 64;
    constexpr int BK  = 32;
    constexpr int TCG = C / 4;
    constexpr int TM  = (BM * C) / 1024;
    constexpr int NVW = C / 32;

    const float* __restrict__ X = (LAYER == 0) ? r_x : g_h;
    const float* __restrict__ W = r_W[LAYER];

    __shared__ float xs[BM][BK];
    __shared__ float ws[BK][C];

    int tid  = threadIdx.x;
    int tc   = tid % TCG;
    int tr   = tid / TCG;
    int row0 = blockIdx.x * BM;

    float acc[TM][4];
#pragma unroll
    for (int i = 0; i < TM; i++)
#pragma unroll
        for (int j = 0; j < 4; j++) acc[i][j] = 0.0f;

    for (int k0 = 0; k0 < K; k0 += BK) {
#pragma unroll
        for (int v = 0; v < 2; v++) {
            int i4 = v * 256 + tid;
            int r  = i4 >> 3;
            int c4 = i4 & 7;
            float4 val = make_float4(0.f, 0.f, 0.f, 0.f);
            if (row0 + r < NN)
                val = *(const float4*)&X[(size_t)(row0 + r) * K + k0 + c4 * 4];
            *(float4*)&xs[r][c4 * 4] = val;
        }
#pragma unroll
        for (int v = 0; v < NVW; v++) {
            int i4 = v * 256 + tid;
            int k  = i4 / (C / 4);
            int c4 = i4 % (C / 4);
            *(float4*)&ws[k][c4 * 4] = *(const float4*)&W[(size_t)(k0 + k) * C + c4 * 4];
        }
        __syncthreads();

#pragma unroll
        for (int kk = 0; kk < BK; kk++) {
            float4 w4 = *(float4*)&ws[kk][tc * 4];
#pragma unroll
            for (int i = 0; i < TM; i++) {
                float xv = xs[tr * TM + i][kk];
                acc[i][0] += xv * w4.x;
                acc[i][1] += xv * w4.y;
                acc[i][2] += xv * w4.z;
                acc[i][3] += xv * w4.w;
            }
        }
        __syncthreads();
    }

#pragma unroll
    for (int i = 0; i < TM; i++) {
        int r = row0 + tr * TM + i;
        if (r < NN) {
            float4 o = make_float4(acc[i][0], acc[i][1], acc[i][2], acc[i][3]);
            *(float4*)&g_feat[(size_t)r * C + tc * 4] = o;
        }
    }
}

// ---------------------------------------------------------------------------
// el/er for both heads of one node per thread, float4 feat loads
// ---------------------------------------------------------------------------
template <int D, int LAYER>
__global__ void attn_kernel() {
    int n = blockIdx.x * blockDim.x + threadIdx.x;
    if (n >= NN) return;
    const float4* f  = (const float4*)(g_feat + (size_t)n * (2 * D));
    const float4* a0 = (const float4*)r_al[LAYER];
    const float4* b0 = (const float4*)r_ar[LAYER];
    float el0 = 0.f, er0 = 0.f, el1 = 0.f, er1 = 0.f;
#pragma unroll
    for (int j = 0; j < D / 4; j++) {
        float4 v0 = f[j];
        float4 v1 = f[D / 4 + j];
        float4 a  = a0[j];
        float4 b  = b0[j];
        float4 a1 = a0[D / 4 + j];
        float4 b1 = b0[D / 4 + j];
        el0 += v0.x * a.x  + v0.y * a.y  + v0.z * a.z  + v0.w * a.w;
        er0 += v0.x * b.x  + v0.y * b.y  + v0.z * b.z  + v0.w * b.w;
        el1 += v1.x * a1.x + v1.y * a1.y + v1.z * a1.z + v1.w * a1.w;
        er1 += v1.x * b1.x + v1.y * b1.y + v1.z * b1.z + v1.w * b1.w;
    }
    g_el[n * 2]     = el0;
    g_er[n * 2]     = er0;
    g_el[n * 2 + 1] = el1;
    g_er[n * 2 + 1] = er1;
}

// ---------------------------------------------------------------------------
// Pass 1: one thread per edge, both heads
// ---------------------------------------------------------------------------
__global__ void edge_pass1() {
    int eid = blockIdx.x * blockDim.x + threadIdx.x;
    if (eid >= EE) return;
    int s = r_src[eid], d = r_dst[eid];
    if ((unsigned)s >= NN || (unsigned)d >= NN) return;
    float v0 = g_el[s * 2]     + g_er[d * 2];
    float v1 = g_el[s * 2 + 1] + g_er[d * 2 + 1];
    v0 = v0 > 0.f ? v0 : NEG_SLOPE * v0;
    v1 = v1 > 0.f ? v1 : NEG_SLOPE * v1;
    g_e[eid * 2]     = v0;
    g_e[eid * 2 + 1] = v1;
    atomicMax(&g_m[d * 2],     encf(v0));
    atomicMax(&g_m[d * 2 + 1], encf(v1));
}

// Pass 2: one thread per edge, both heads
__global__ void edge_pass2() {
    int eid = blockIdx.x * blockDim.x + threadIdx.x;
    if (eid >= EE) return;
    int d = r_dst[eid];
    if ((unsigned)d >= NN) return;
    float m0 = decf(g_m[d * 2]);
    float m1 = decf(g_m[d * 2 + 1]);
    float e0 = __expf(g_e[eid * 2]     - m0);
    float e1 = __expf(g_e[eid * 2 + 1] - m1);
    g_e[eid * 2]     = e0;
    g_e[eid * 2 + 1] = e1;
    atomicAdd(&g_s[d * 2],     e0);
    atomicAdd(&g_s[d * 2 + 1], e1);
}

// ---------------------------------------------------------------------------
// Pass 3: 8 lanes per (edge, head); float4 vector atomics (RED.128)
// ---------------------------------------------------------------------------
template <int D>
__global__ void edge_pass3() {
    int t = blockIdx.x * blockDim.x + threadIdx.x;
    if (t >= EE * 2 * 8) return;
    int lane = t & 7, eh = t >> 3;
    int eid = eh >> 1, h = eh & 1;
    int s = r_src[eid], d = r_dst[eid];
    if ((unsigned)s >= NN || (unsigned)d >= NN) return;
    float alpha = g_e[eh] / g_s[d * 2 + h];
    const float4* f = (const float4*)(g_feat + (size_t)s * (2 * D) + h * D);
    float4*       r = (float4*)(g_rst  + (size_t)d * (2 * D) + h * D);
#pragma unroll
    for (int k = 0; k < D / 32; k++) {
        float4 v = f[lane + 8 * k];
        atomicAdd(&r[lane + 8 * k],
                  make_float4(v.x * alpha, v.y * alpha, v.z * alpha, v.w * alpha));
    }
}

// ---------------------------------------------------------------------------
template <int LAYER>
__global__ void epi01() {
    int i = blockIdx.x * blockDim.x + threadIdx.x;   // float4 index
    if (i >= NN * 16) return;
    const float4* b4 = (const float4*)r_b[LAYER];
    float4 v = ((const float4*)g_rst)[i];
    float4 b = b4[i & 15];
    v.x = fmaxf(v.x + b.x, 0.f);
    v.y = fmaxf(v.y + b.y, 0.f);
    v.z = fmaxf(v.z + b.z, 0.f);
    v.w = fmaxf(v.w + b.w, 0.f);
    ((float4*)g_h)[i] = v;
}

__global__ void epi2(float* __restrict__ out) {
    int i = blockIdx.x * blockDim.x + threadIdx.x;   // float4 index over [N,64]
    if (i >= NN * 16) return;
    int n = i >> 4, j = i & 15;
    const float4* b4 = (const float4*)r_b[2];
    float4 v0 = ((const float4*)g_rst)[n * 32 + j];
    float4 v1 = ((const float4*)g_rst)[n * 32 + 16 + j];
    float4 c0 = b4[j];
    float4 c1 = b4[16 + j];
    float4 o;
    o.x = 0.5f * (v0.x + c0.x + v1.x + c1.x);
    o.y = 0.5f * (v0.y + c0.y + v1.y + c1.y);
    o.z = 0.5f * (v0.z + c0.z + v1.z + c1.z);
    o.w = 0.5f * (v0.w + c0.w + v1.w + c1.w);
    ((float4*)out)[i] = o;
}

// ---------------------------------------------------------------------------
extern "C" void kernel_launch(void* const* d_in, const int* in_sizes, int n_in,
                              void* d_out, int out_size) {
    InPtrs in;
    in.n = (n_in < 16) ? n_in : 16;
    for (int i = 0; i < 16; i++) {
        in.p[i]  = (i < n_in) ? d_in[i] : nullptr;
        in.sz[i] = (i < n_in) ? in_sizes[i] : 0;
    }
    float* out = (float*)d_out;

    const int BS = 256;
    const int gN    = (NN + BS - 1) / BS;
    const int gE    = (EE + BS - 1) / BS;
    const int gE16  = (EE * 16 + BS - 1) / BS;
    const int gN16  = (NN * 16 + BS - 1) / BS;
    const int gZ64  = (NN * 16 + BS - 1) / BS;
    const int gZ128 = (NN * 32 + BS - 1) / BS;
    const int gGemm = (NN + 63) / 64;

    classify_kernel<<<1, 256>>>(in);

    // ---- Layer 0: 128 -> 64 ----
    zero_scratch<<<gZ64, BS>>>(NN * 16);
    gemm_kernel<128, 64, 0><<<gGemm, BS>>>();
    attn_kernel<32, 0><<<gN, BS>>>();
    edge_pass1<<<gE, BS>>>();
    edge_pass2<<<gE, BS>>>();
    edge_pass3<32><<<gE16, BS>>>();
    epi01<0><<<gN16, BS>>>();

    // ---- Layer 1: 64 -> 64 ----
    zero_scratch<<<gZ64, BS>>>(NN * 16);
    gemm_kernel<64, 64, 1><<<gGemm, BS>>>();
    attn_kernel<32, 1><<<gN, BS>>>();
    edge_pass1<<<gE, BS>>>();
    edge_pass2<<<gE, BS>>>();
    edge_pass3<32><<<gE16, BS>>>();
    epi01<1><<<gN16, BS>>>();

    // ---- Layer 2: 64 -> 128 (2 heads x 64), mean over heads ----
    zero_scratch<<<gZ128, BS>>>(NN * 32);
    gemm_kernel<64, 128, 2><<<gGemm, BS>>>();
    attn_kernel<64, 2><<<gN, BS>>>();
    edge_pass1<<<gE, BS>>>();
    edge_pass2<<<gE, BS>>>();
    edge_pass3<64><<<gE16 * 2, BS>>>();
    epi2<<<gN16, BS>>>(out);
}

// round 7
// speedup vs baseline: 1.6930x; 1.3912x over previous
#include <cuda_runtime.h>
#include <cuda_bf16.h>

#define NN 50000
#define EE 800000
#define NEG_SLOPE 0.2f
#define NEG_INF __int_as_float(0xff800000)

// ---------------------------------------------------------------------------
// Scratch (device globals; referenced ONLY from device code)
// ---------------------------------------------------------------------------
__device__ __align__(16) float g_feat[NN * 128];
__device__ __align__(16) float g_h   [NN * 64];
__device__ __align__(16) float g_el  [NN * 2];
__device__ __align__(16) float g_er  [NN * 2];
__device__ int g_rowptr[NN + 1];
__device__ int g_cur[NN];
__device__ int g_csrc[EE];

__device__ const float* r_x;
__device__ const int*   r_src;
__device__ const int*   r_dst;
__device__ const float* r_W[3];
__device__ const float* r_al[3];
__device__ const float* r_ar[3];
__device__ const float* r_b[3];

struct InPtrs {
    const void* p[16];
    int sz[16];
    int n;
};

__device__ __forceinline__ int norm_size(int sz) {
    switch (sz) {
        case 6400000: case 800000: case 8192: case 4096: case 128: case 64:
            return sz;
        case 25600000: return 6400000;
        case 3200000:  return 800000;
        case 32768:    return 8192;
        case 16384:    return 4096;
        case 512:      return 128;
        case 256:      return 64;
        default:       return -1;
    }
}

// ---------------------------------------------------------------------------
// Content/shape-based input classification with positional fallback.
// ---------------------------------------------------------------------------
__global__ __launch_bounds__(256) void classify_kernel(InPtrs in) {
    __shared__ float sred[256];
    __shared__ int sh8192[2];
    __shared__ int s_ok;

    if (threadIdx.x == 0) {
        int c = 0;
        sh8192[0] = sh8192[1] = 0;
        for (int i = 0; i < in.n && i < 16; i++)
            if (norm_size(in.sz[i]) == 8192 && c < 2) sh8192[c++] = i;
        s_ok = (c == 2);
    }
    __syncthreads();

    float q[2];
    for (int t = 0; t < 2; t++) {
        const float* p = (const float*)in.p[sh8192[t]];
        float s = 0.f;
        if (s_ok)
            for (int i = threadIdx.x; i < 8192; i += 256) { float v = p[i]; s += v * v; }
        sred[threadIdx.x] = s;
        __syncthreads();
        for (int st = 128; st > 0; st >>= 1) {
            if (threadIdx.x < st) sred[threadIdx.x] += sred[threadIdx.x + st];
            __syncthreads();
        }
        q[t] = sred[0];
        __syncthreads();
    }

    if (threadIdx.x != 0) return;

    int iX = -1, iW1 = -1, i800k[2] = {-1, -1}, i128[3] = {-1, -1, -1}, i64[6];
    int c800k = 0, c128 = 0, c64 = 0;
    for (int i = 0; i < 6; i++) i64[i] = -1;
    for (int i = 0; i < in.n && i < 16; i++) {
        int n = norm_size(in.sz[i]);
        if      (n == 6400000) iX = i;
        else if (n == 4096)    iW1 = i;
        else if (n == 800000)  { if (c800k < 2) i800k[c800k++] = i; }
        else if (n == 128)     { if (c128 < 3)  i128[c128++]  = i; }
        else if (n == 64)      { if (c64 < 6)   i64[c64++]    = i; }
    }

    bool ok = s_ok && iX >= 0 && iW1 >= 0 && c800k == 2 && c128 == 3 && c64 == 6;

    int ix, isrc, idst, iW0, iW2, ial[3], iar[3], ib[3];
    if (!ok) {
        ix = 0; isrc = 1; idst = 2;
        iW0 = 3;  ial[0] = 4;  iar[0] = 5;  ib[0] = 6;
        iW1 = 7;  ial[1] = 8;  iar[1] = 9;  ib[1] = 10;
        iW2 = 11; ial[2] = 12; iar[2] = 13; ib[2] = 14;
    } else {
        ix  = iX;
        iW0 = (q[0] < q[1]) ? sh8192[0] : sh8192[1];
        iW2 = (q[0] < q[1]) ? sh8192[1] : sh8192[0];

        int zs[6], zn = 0, ns[6], nn = 0;
        for (int g = 0; g < 6; g++) {
            const float* p = (const float*)in.p[i64[g]];
            float s = 0.f;
            for (int k = 0; k < 64; k++) s += fabsf(p[k]);
            if (s == 0.0f) { if (zn < 6) zs[zn++] = g; }
            else           { if (nn < 6) ns[nn++] = g; }
        }
        bool interleaved = (zn < 1) || (zs[0] == 2);
        if (zn >= 2 && nn >= 4) {
            ib[0] = i64[zs[0]]; ib[1] = i64[zs[1]];
            if (interleaved) { ial[0]=i64[ns[0]]; iar[0]=i64[ns[1]]; ial[1]=i64[ns[2]]; iar[1]=i64[ns[3]]; }
            else             { ial[0]=i64[ns[0]]; ial[1]=i64[ns[1]]; iar[0]=i64[ns[2]]; iar[1]=i64[ns[3]]; }
        } else {
            ib[0]=i64[2]; ib[1]=i64[5]; ial[0]=i64[0]; iar[0]=i64[1]; ial[1]=i64[3]; iar[1]=i64[4];
        }

        int a2 = -1, r2 = -1, bz = -1;
        for (int g = 0; g < 3; g++) {
            const float* p = (const float*)in.p[i128[g]];
            float s = 0.f;
            for (int k = 0; k < 128; k++) s += fabsf(p[k]);
            if (s == 0.0f)   bz = i128[g];
            else if (a2 < 0) a2 = i128[g];
            else             r2 = i128[g];
        }
        ial[2] = a2; iar[2] = r2; ib[2] = (bz >= 0) ? bz : i128[2];

        isrc = interleaved ? i800k[0] : i800k[1];
        idst = interleaved ? i800k[1] : i800k[0];
    }

    r_x    = (const float*)in.p[ix];
    r_src  = (const int*)  in.p[isrc];
    r_dst  = (const int*)  in.p[idst];
    r_W[0] = (const float*)in.p[iW0];
    r_W[1] = (const float*)in.p[iW1];
    r_W[2] = (const float*)in.p[iW2];
    for (int l = 0; l < 3; l++) {
        r_al[l] = (const float*)in.p[ial[l]];
        r_ar[l] = (const float*)in.p[iar[l]];
        r_b [l] = (const float*)in.p[ib[l]];
    }
}

// ---------------------------------------------------------------------------
// CSR construction (once per call; graph identical across layers)
// ---------------------------------------------------------------------------
__global__ void csr_zero() {
    int i = blockIdx.x * blockDim.x + threadIdx.x;
    if (i < NN) g_cur[i] = 0;
}

__global__ void csr_hist() {
    int e = blockIdx.x * blockDim.x + threadIdx.x;
    if (e >= EE) return;
    int d = r_dst[e];
    if ((unsigned)d < NN) atomicAdd(&g_cur[d], 1);
}

// Single-block exclusive scan of degrees -> rowptr, and reset cursor=rowptr
__global__ __launch_bounds__(1024) void csr_scan() {
    __shared__ int ssum[1024];
    int tid = threadIdx.x;
    const int CH = (NN + 1023) / 1024;   // 49
    int base = tid * CH;
    int end  = min(base + CH, NN);
    int sum = 0;
    for (int i = base; i < end; i++) sum += g_cur[i];
    ssum[tid] = sum;
    __syncthreads();
    // Hillis-Steele inclusive scan
    for (int off = 1; off < 1024; off <<= 1) {
        int t = (tid >= off) ? ssum[tid - off] : 0;
        __syncthreads();
        ssum[tid] += t;
        __syncthreads();
    }
    int run = ssum[tid] - sum;           // exclusive prefix for this chunk
    for (int i = base; i < end; i++) {
        int dg = g_cur[i];
        g_rowptr[i] = run;
        g_cur[i]    = run;               // cursor starts at rowptr
        run += dg;
    }
    if (tid == 1023) g_rowptr[NN] = ssum[1023];
}

__global__ void csr_scatter() {
    int e = blockIdx.x * blockDim.x + threadIdx.x;
    if (e >= EE) return;
    int d = r_dst[e], s = r_src[e];
    if ((unsigned)d >= NN || (unsigned)s >= NN) return;
    int pos = atomicAdd(&g_cur[d], 1);
    g_csrc[pos] = s;
}

// ---------------------------------------------------------------------------
// GEMM: g_feat[N, C] = X[N, K] @ W[K, C]
// ---------------------------------------------------------------------------
template <int K, int C, int LAYER>
__global__ __launch_bounds__(256) void gemm_kernel() {
    constexpr int BM  = 64;
    constexpr int BK  = 32;
    constexpr int TCG = C / 4;
    constexpr int TM  = (BM * C) / 1024;
    constexpr int NVW = C / 32;

    const float* __restrict__ X = (LAYER == 0) ? r_x : g_h;
    const float* __restrict__ W = r_W[LAYER];

    __shared__ float xs[BM][BK];
    __shared__ float ws[BK][C];

    int tid  = threadIdx.x;
    int tc   = tid % TCG;
    int tr   = tid / TCG;
    int row0 = blockIdx.x * BM;

    float acc[TM][4];
#pragma unroll
    for (int i = 0; i < TM; i++)
#pragma unroll
        for (int j = 0; j < 4; j++) acc[i][j] = 0.0f;

    for (int k0 = 0; k0 < K; k0 += BK) {
#pragma unroll
        for (int v = 0; v < 2; v++) {
            int i4 = v * 256 + tid;
            int r  = i4 >> 3;
            int c4 = i4 & 7;
            float4 val = make_float4(0.f, 0.f, 0.f, 0.f);
            if (row0 + r < NN)
                val = *(const float4*)&X[(size_t)(row0 + r) * K + k0 + c4 * 4];
            *(float4*)&xs[r][c4 * 4] = val;
        }
#pragma unroll
        for (int v = 0; v < NVW; v++) {
            int i4 = v * 256 + tid;
            int k  = i4 / (C / 4);
            int c4 = i4 % (C / 4);
            *(float4*)&ws[k][c4 * 4] = *(const float4*)&W[(size_t)(k0 + k) * C + c4 * 4];
        }
        __syncthreads();

#pragma unroll
        for (int kk = 0; kk < BK; kk++) {
            float4 w4 = *(float4*)&ws[kk][tc * 4];
#pragma unroll
            for (int i = 0; i < TM; i++) {
                float xv = xs[tr * TM + i][kk];
                acc[i][0] += xv * w4.x;
                acc[i][1] += xv * w4.y;
                acc[i][2] += xv * w4.z;
                acc[i][3] += xv * w4.w;
            }
        }
        __syncthreads();
    }

#pragma unroll
    for (int i = 0; i < TM; i++) {
        int r = row0 + tr * TM + i;
        if (r < NN) {
            float4 o = make_float4(acc[i][0], acc[i][1], acc[i][2], acc[i][3]);
            *(float4*)&g_feat[(size_t)r * C + tc * 4] = o;
        }
    }
}

// ---------------------------------------------------------------------------
// el/er for both heads of one node per thread
// ---------------------------------------------------------------------------
template <int D, int LAYER>
__global__ void attn_kernel() {
    int n = blockIdx.x * blockDim.x + threadIdx.x;
    if (n >= NN) return;
    const float4* f  = (const float4*)(g_feat + (size_t)n * (2 * D));
    const float4* a0 = (const float4*)r_al[LAYER];
    const float4* b0 = (const float4*)r_ar[LAYER];
    float el0 = 0.f, er0 = 0.f, el1 = 0.f, er1 = 0.f;
#pragma unroll
    for (int j = 0; j < D / 4; j++) {
        float4 v0 = f[j];
        float4 v1 = f[D / 4 + j];
        float4 a  = a0[j];
        float4 b  = b0[j];
        float4 a1 = a0[D / 4 + j];
        float4 b1 = b0[D / 4 + j];
        el0 += v0.x * a.x  + v0.y * a.y  + v0.z * a.z  + v0.w * a.w;
        er0 += v0.x * b.x  + v0.y * b.y  + v0.z * b.z  + v0.w * b.w;
        el1 += v1.x * a1.x + v1.y * a1.y + v1.z * a1.z + v1.w * a1.w;
        er1 += v1.x * b1.x + v1.y * b1.y + v1.z * b1.z + v1.w * b1.w;
    }
    g_el[n * 2]     = el0;
    g_er[n * 2]     = er0;
    g_el[n * 2 + 1] = el1;
    g_er[n * 2 + 1] = er1;
}

// ---------------------------------------------------------------------------
// Fused per-node softmax + aggregation. Warp per dst node, no atomics.
// DT = total channels (2 heads). FINAL: head-mean into out.
// ---------------------------------------------------------------------------
template <int DT, int LAYER, bool FINAL>
__global__ __launch_bounds__(256) void agg_kernel(float* __restrict__ out) {
    __shared__ float2 s_alpha[8][64];

    int warp = threadIdx.x >> 5, lane = threadIdx.x & 31;
    int d = blockIdx.x * 8 + warp;
    if (d >= NN) return;

    int base = g_rowptr[d];
    int deg  = g_rowptr[d + 1] - base;

    float2 er = *(const float2*)&g_el[0 - 0 + 0];  // placeholder (overwritten)
    er = *(const float2*)&g_er[d * 2];

    // --- phase A1: max over edges (warp-strided) ---
    float m0 = NEG_INF, m1 = NEG_INF;
    for (int j = lane; j < deg; j += 32) {
        int sj = g_csrc[base + j];
        float2 el = *(const float2*)&g_el[sj * 2];
        float e0 = el.x + er.x; e0 = e0 > 0.f ? e0 : NEG_SLOPE * e0;
        float e1 = el.y + er.y; e1 = e1 > 0.f ? e1 : NEG_SLOPE * e1;
        m0 = fmaxf(m0, e0);
        m1 = fmaxf(m1, e1);
    }
#pragma unroll
    for (int off = 16; off > 0; off >>= 1) {
        m0 = fmaxf(m0, __shfl_xor_sync(0xffffffffu, m0, off));
        m1 = fmaxf(m1, __shfl_xor_sync(0xffffffffu, m1, off));
    }

    // --- phase A2: sum of exp (warp-strided, recompute e) ---
    float s0 = 0.f, s1 = 0.f;
    for (int j = lane; j < deg; j += 32) {
        int sj = g_csrc[base + j];
        float2 el = *(const float2*)&g_el[sj * 2];
        float e0 = el.x + er.x; e0 = e0 > 0.f ? e0 : NEG_SLOPE * e0;
        float e1 = el.y + er.y; e1 = e1 > 0.f ? e1 : NEG_SLOPE * e1;
        s0 += __expf(e0 - m0);
        s1 += __expf(e1 - m1);
    }
#pragma unroll
    for (int off = 16; off > 0; off >>= 1) {
        s0 += __shfl_xor_sync(0xffffffffu, s0, off);
        s1 += __shfl_xor_sync(0xffffffffu, s1, off);
    }
    float inv0 = (s0 > 0.f) ? 1.f / s0 : 0.f;
    float inv1 = (s1 > 0.f) ? 1.f / s1 : 0.f;

    // --- phase B: chunked alpha -> smem, then coalesced weighted gather ---
    constexpr int NACC = DT / 32;     // 2 (layers 0/1) or 4 (layer 2)
    float acc[NACC];
#pragma unroll
    for (int k = 0; k < NACC; k++) acc[k] = 0.f;

    for (int c0 = 0; c0 < deg; c0 += 64) {
        int cnt = min(64, deg - c0);
        for (int j = lane; j < cnt; j += 32) {
            int sj = g_csrc[base + c0 + j];
            float2 el = *(const float2*)&g_el[sj * 2];
            float e0 = el.x + er.x; e0 = e0 > 0.f ? e0 : NEG_SLOPE * e0;
            float e1 = el.y + er.y; e1 = e1 > 0.f ? e1 : NEG_SLOPE * e1;
            s_alpha[warp][j] = make_float2(__expf(e0 - m0) * inv0,
                                           __expf(e1 - m1) * inv1);
        }
        __syncwarp();
        for (int j = 0; j < cnt; j++) {
            float2 al = s_alpha[warp][j];
            int sj = g_csrc[base + c0 + j];
            float a = (lane < 16) ? al.x : al.y;
            if (NACC == 2) {
                float2 v = ((const float2*)(g_feat + (size_t)sj * DT))[lane];
                acc[0] += a * v.x;
                acc[1] += a * v.y;
            } else {
                float4 v = ((const float4*)(g_feat + (size_t)sj * DT))[lane];
                acc[0] += a * v.x;
                acc[1] += a * v.y;
                acc[2] += a * v.z;
                acc[3] += a * v.w;
            }
        }
        __syncwarp();
    }

    // --- epilogue ---
    if (!FINAL) {
        float2 b = ((const float2*)r_b[LAYER])[lane];
        float v0 = acc[0] + b.x;
        float v1 = acc[1] + b.y;
        ((float2*)(g_h + (size_t)d * 64))[lane] =
            make_float2(v0 > 0.f ? v0 : 0.f, v1 > 0.f ? v1 : 0.f);
    } else {
        float4 b = ((const float4*)r_b[2])[lane];
        float v0 = acc[0] + b.x;
        float v1 = acc[1] + b.y;
        float v2 = acc[2] + b.z;
        float v3 = acc[3] + b.w;
        float p0 = __shfl_down_sync(0xffffffffu, v0, 16);
        float p1 = __shfl_down_sync(0xffffffffu, v1, 16);
        float p2 = __shfl_down_sync(0xffffffffu, v2, 16);
        float p3 = __shfl_down_sync(0xffffffffu, v3, 16);
        if (lane < 16) {
            float4 o = make_float4(0.5f * (v0 + p0), 0.5f * (v1 + p1),
                                   0.5f * (v2 + p2), 0.5f * (v3 + p3));
            ((float4*)(out + (size_t)d * 64))[lane] = o;
        }
    }
}

// ---------------------------------------------------------------------------
extern "C" void kernel_launch(void* const* d_in, const int* in_sizes, int n_in,
                              void* d_out, int out_size) {
    InPtrs in;
    in.n = (n_in < 16) ? n_in : 16;
    for (int i = 0; i < 16; i++) {
        in.p[i]  = (i < n_in) ? d_in[i] : nullptr;
        in.sz[i] = (i < n_in) ? in_sizes[i] : 0;
    }
    float* out = (float*)d_out;

    const int BS = 256;
    const int gN    = (NN + BS - 1) / BS;
    const int gE    = (EE + BS - 1) / BS;
    const int gGemm = (NN + 63) / 64;
    const int gAgg  = (NN + 7) / 8;

    classify_kernel<<<1, 256>>>(in);

    // CSR build (once; reused by all layers)
    csr_zero<<<gN, BS>>>();
    csr_hist<<<gE, BS>>>();
    csr_scan<<<1, 1024>>>();
    csr_scatter<<<gE, BS>>>();

    // ---- Layer 0: 128 -> 64 ----
    gemm_kernel<128, 64, 0><<<gGemm, BS>>>();
    attn_kernel<32, 0><<<gN, BS>>>();
    agg_kernel<64, 0, false><<<gAgg, BS>>>(nullptr);

    // ---- Layer 1: 64 -> 64 ----
    gemm_kernel<64, 64, 1><<<gGemm, BS>>>();
    attn_kernel<32, 1><<<gN, BS>>>();
    agg_kernel<64, 1, false><<<gAgg, BS>>>(nullptr);

    // ---- Layer 2: 64 -> 128, head-mean ----
    gemm_kernel<64, 128, 2><<<gGemm, BS>>>();
    attn_kernel<64, 2><<<gN, BS>>>();
    agg_kernel<128, 2, true><<<gAgg, BS>>>(out);
}